// round 1
// baseline (speedup 1.0000x reference)
#include <cuda_runtime.h>
#include <cstdint>
#include <cstddef>

// Problem dims
static constexpr int B_ = 16;
static constexpr int S_ = 2048;
static constexpr int H_ = 1024;
static constexpr int M  = B_ * S_;   // 32768 tokens
static constexpr int N  = 3 * H_;    // 3072
static constexpr int K  = H_;        // 1024 (D)

// GEMM tiling
static constexpr int BM = 128, BN = 128, BK = 16;
static constexpr int KS = BK + 4;    // padded smem stride (conflict-free frag loads)

// Scratch (allocation-free rule: __device__ globals)
__device__ float g_z[(size_t)M * H_];   // tanh(z)
__device__ float g_f[(size_t)M * H_];   // sigmoid(f)

__device__ __forceinline__ float fsig(float x) {
    float e = __expf(-x);
    return __fdividef(1.0f, 1.0f + e);
}
__device__ __forceinline__ float ftanh(float x) {
    // tanh(x) = 2*sigmoid(2x) - 1 ; abs err ~1e-6, fine for 1e-3 budget
    return fmaf(2.0f, fsig(2.0f * x), -1.0f);
}

// ---------------------------------------------------------------------------
// Fused GEMM + bias + activations.
//   y[m, n] = sum_k inp[m,k] * W[n,k] + b[n]
//   n <  H : g_z = tanh(y)
//   n < 2H : g_f = sigmoid(y)
//   else   : out = sigmoid(y)    (scan multiplies in-place later)
// TF32 mma.sync, 128x128x16 tiles, cp.async double buffer.
// ---------------------------------------------------------------------------
__global__ __launch_bounds__(256) void qrnn_gemm(
    const float* __restrict__ A, const float* __restrict__ Wt,
    const float* __restrict__ bias, float* __restrict__ out)
{
    __shared__ float As[2][BM * KS];
    __shared__ float Bs[2][BN * KS];

    const int tid  = threadIdx.x;
    const int lane = tid & 31, wid = tid >> 5;
    const int wm = wid >> 2;        // 0..1  -> 64 rows each
    const int wn = wid & 3;         // 0..3  -> 32 cols each
    const int g   = lane >> 2;      // group id 0..7
    const int tig = lane & 3;       // thread-in-group 0..3
    const int m0 = blockIdx.y * BM;
    const int n0 = blockIdx.x * BN;

    float acc[4][4][4];
    #pragma unroll
    for (int mi = 0; mi < 4; mi++)
        #pragma unroll
        for (int ni = 0; ni < 4; ni++)
            #pragma unroll
            for (int r = 0; r < 4; r++) acc[mi][ni][r] = 0.0f;

    // --- async tile prefetch: 512 float4 per operand per stage, 2 per thread
    auto prefetch = [&](int kt, int s) {
        const int k0 = kt * BK;
        #pragma unroll
        for (int i = 0; i < 2; i++) {
            int lin = tid + i * 256;
            int row = lin >> 2;            // 0..127
            int c4  = (lin & 3) * 4;       // 0,4,8,12
            {
                const float* gp = A + (size_t)(m0 + row) * K + k0 + c4;
                uint32_t sa = (uint32_t)__cvta_generic_to_shared(&As[s][row * KS + c4]);
                asm volatile("cp.async.ca.shared.global [%0], [%1], 16;\n" :: "r"(sa), "l"(gp));
            }
            {
                const float* gp = Wt + (size_t)(n0 + row) * K + k0 + c4;
                uint32_t sa = (uint32_t)__cvta_generic_to_shared(&Bs[s][row * KS + c4]);
                asm volatile("cp.async.ca.shared.global [%0], [%1], 16;\n" :: "r"(sa), "l"(gp));
            }
        }
        asm volatile("cp.async.commit_group;\n");
    };

    constexpr int NK = K / BK;   // 64
    prefetch(0, 0);

    for (int kt = 0; kt < NK; kt++) {
        const int s = kt & 1;
        if (kt + 1 < NK) {
            prefetch(kt + 1, s ^ 1);
            asm volatile("cp.async.wait_group 1;\n");
        } else {
            asm volatile("cp.async.wait_group 0;\n");
        }
        __syncthreads();

        const float* as = As[s];
        const float* bs = Bs[s];

        #pragma unroll
        for (int kk = 0; kk < BK; kk += 8) {
            uint32_t afr[4][4], bfr[4][2];
            #pragma unroll
            for (int mi = 0; mi < 4; mi++) {
                int m = wm * 64 + mi * 16;
                afr[mi][0] = __float_as_uint(as[(m + g    ) * KS + kk + tig    ]);
                afr[mi][1] = __float_as_uint(as[(m + g + 8) * KS + kk + tig    ]);
                afr[mi][2] = __float_as_uint(as[(m + g    ) * KS + kk + tig + 4]);
                afr[mi][3] = __float_as_uint(as[(m + g + 8) * KS + kk + tig + 4]);
            }
            #pragma unroll
            for (int ni = 0; ni < 4; ni++) {
                int n = wn * 32 + ni * 8;
                bfr[ni][0] = __float_as_uint(bs[(n + g) * KS + kk + tig    ]);
                bfr[ni][1] = __float_as_uint(bs[(n + g) * KS + kk + tig + 4]);
            }
            #pragma unroll
            for (int mi = 0; mi < 4; mi++)
                #pragma unroll
                for (int ni = 0; ni < 4; ni++)
                    asm volatile(
                        "mma.sync.aligned.m16n8k8.row.col.f32.tf32.tf32.f32 "
                        "{%0,%1,%2,%3}, {%4,%5,%6,%7}, {%8,%9}, {%0,%1,%2,%3};\n"
                        : "+f"(acc[mi][ni][0]), "+f"(acc[mi][ni][1]),
                          "+f"(acc[mi][ni][2]), "+f"(acc[mi][ni][3])
                        : "r"(afr[mi][0]), "r"(afr[mi][1]), "r"(afr[mi][2]), "r"(afr[mi][3]),
                          "r"(bfr[ni][0]), "r"(bfr[ni][1]));
        }
        __syncthreads();
    }

    // --- epilogue: bias + activation, scatter into gate arrays
    #pragma unroll
    for (int mi = 0; mi < 4; mi++) {
        #pragma unroll
        for (int ni = 0; ni < 4; ni++) {
            int col0 = n0 + wn * 32 + ni * 8 + tig * 2;
            #pragma unroll
            for (int r = 0; r < 4; r++) {
                int row = m0 + wm * 64 + mi * 16 + g + ((r >= 2) ? 8 : 0);
                int col = col0 + (r & 1);
                float v = acc[mi][ni][r] + __ldg(&bias[col]);
                int gate = col >> 10;            // col / H
                int hcol = col & (H_ - 1);
                size_t p = (size_t)row * H_ + hcol;
                if (gate == 0)      g_z[p] = ftanh(v);
                else if (gate == 1) g_f[p] = fsig(v);
                else                out[p] = fsig(v);      // sigmoid(o) staged in out
            }
        }
    }
}

// ---------------------------------------------------------------------------
// Sequential recurrence: one thread per (b, h) chain, coalesced over h.
//   h_t = f*z + (1-f)*h = h + f*(z - h)
//   out[b,t,h] = sig_o (already in out) * h_t ;  c_last appended after out.
// Unroll-16 with manual next-group prefetch to keep loads in flight.
// ---------------------------------------------------------------------------
__global__ __launch_bounds__(256) void qrnn_scan(float* __restrict__ out, int write_clast)
{
    const int idx = blockIdx.x * blockDim.x + threadIdx.x;   // 0 .. B*H-1
    const int b = idx >> 10;            // / H
    const int h = idx & (H_ - 1);
    const size_t base = (size_t)b * S_ * H_ + h;

    constexpr int U = 16;
    float z[U], f[U], o[U];
    #pragma unroll
    for (int j = 0; j < U; j++) {
        size_t p = base + (size_t)j * H_;
        z[j] = g_z[p]; f[j] = g_f[p]; o[j] = out[p];
    }

    float hh = 0.0f;
    for (int t = 0; t < S_; t += U) {
        float zn[U], fn[U], on[U];
        if (t + U < S_) {
            #pragma unroll
            for (int j = 0; j < U; j++) {
                size_t p = base + (size_t)(t + U + j) * H_;
                zn[j] = g_z[p]; fn[j] = g_f[p]; on[j] = out[p];
            }
        }
        #pragma unroll
        for (int j = 0; j < U; j++) {
            hh = fmaf(f[j], z[j] - hh, hh);
            out[base + (size_t)(t + j) * H_] = o[j] * hh;
        }
        #pragma unroll
        for (int j = 0; j < U; j++) { z[j] = zn[j]; f[j] = fn[j]; o[j] = on[j]; }
    }

    if (write_clast) out[(size_t)B_ * S_ * H_ + idx] = hh;
}

// ---------------------------------------------------------------------------
extern "C" void kernel_launch(void* const* d_in, const int* in_sizes, int n_in,
                              void* d_out, int out_size)
{
    const float* inp  = (const float*)d_in[0];   // [B, S, D] f32
    const float* Wt   = (const float*)d_in[1];   // [3H, D]   f32
    const float* bias = (const float*)d_in[2];   // [3H]      f32
    float* out = (float*)d_out;

    dim3 grid(N / BN, M / BM);   // N fastest -> A-tile reuse hits L2
    qrnn_gemm<<<grid, 256>>>(inp, Wt, bias, out);

    const long long need = (long long)M * H_ + (long long)B_ * H_;
    int write_clast = ((long long)out_size >= need) ? 1 : 0;
    qrnn_scan<<<(B_ * H_) / 256, 256>>>(out, write_clast);
}

// round 3
// speedup vs baseline: 1.9788x; 1.9788x over previous
#include <cuda_runtime.h>
#include <cuda_fp16.h>
#include <cstdint>
#include <cstddef>

// Problem dims
static constexpr int B_ = 16;
static constexpr int S_ = 2048;
static constexpr int H_ = 1024;
static constexpr int M  = B_ * S_;   // 32768
static constexpr int N3 = 3 * H_;    // 3072
static constexpr int K  = H_;        // 1024

// GEMM tiling (fp16 m16n8k16 path)
static constexpr int BM = 128, BN = 128, BK = 32;
static constexpr int NK = K / BK;                 // 32 k-chunks
static constexpr int STAGES = 3;
static constexpr int RS = 40;                     // smem row stride in halves (80B, conflict-free)
static constexpr int STAGE_HALVES = 128 * RS;     // per operand
static constexpr int STAGE_BYTES  = 2 * STAGE_HALVES * 2;   // A+B = 20480 B
static constexpr int SMEM_TOTAL   = STAGES * STAGE_BYTES;   // 61440 B

// Scratch (__device__ globals: allocation-free rule)
__device__ __half g_Ah[(size_t)M * K];    // fp16 copy of inp
__device__ __half g_Wh[(size_t)N3 * K];   // fp16 copy of W
__device__ float  g_z[(size_t)M * H_];    // tanh(z)
__device__ float  g_f[(size_t)M * H_];    // sigmoid(f)

__device__ __forceinline__ float fsig(float x) {
    float e = __expf(-x);
    return __fdividef(1.0f, 1.0f + e);
}
__device__ __forceinline__ float ftanh(float x) {
    return fmaf(2.0f, fsig(2.0f * x), -1.0f);
}

__device__ __forceinline__ uint32_t smem_u32(const void* p) {
    uint32_t a;
    asm("{ .reg .u64 t; cvta.to.shared.u64 t, %1; cvt.u32.u64 %0, t; }" : "=r"(a) : "l"(p));
    return a;
}
__device__ __forceinline__ void cp_async16(uint32_t sa, const void* g) {
    asm volatile("cp.async.cg.shared.global [%0], [%1], 16;\n" :: "r"(sa), "l"(g));
}
__device__ __forceinline__ void ldmatrix_x4(uint32_t* r, uint32_t addr) {
    asm volatile("ldmatrix.sync.aligned.m8n8.x4.shared.b16 {%0,%1,%2,%3}, [%4];"
                 : "=r"(r[0]), "=r"(r[1]), "=r"(r[2]), "=r"(r[3]) : "r"(addr));
}
__device__ __forceinline__ void mma16816(float* d, const uint32_t* a, const uint32_t* b) {
    asm volatile(
        "mma.sync.aligned.m16n8k16.row.col.f32.f16.f16.f32 "
        "{%0,%1,%2,%3}, {%4,%5,%6,%7}, {%8,%9}, {%0,%1,%2,%3};\n"
        : "+f"(d[0]), "+f"(d[1]), "+f"(d[2]), "+f"(d[3])
        : "r"(a[0]), "r"(a[1]), "r"(a[2]), "r"(a[3]), "r"(b[0]), "r"(b[1]));
}

// ---------------------------------------------------------------------------
// fp32 -> fp16 conversion (grid-stride-free, exact cover; n % 8 == 0)
// ---------------------------------------------------------------------------
__global__ __launch_bounds__(256) void cvt_f2h(const float* __restrict__ src,
                                               __half* __restrict__ dst, int n)
{
    int i = (blockIdx.x * 256 + threadIdx.x) * 8;
    if (i >= n) return;
    float4 a = *(const float4*)(src + i);
    float4 b = *(const float4*)(src + i + 4);
    __half2 h0 = __floats2half2_rn(a.x, a.y);
    __half2 h1 = __floats2half2_rn(a.z, a.w);
    __half2 h2 = __floats2half2_rn(b.x, b.y);
    __half2 h3 = __floats2half2_rn(b.z, b.w);
    uint4 o;
    o.x = *(uint32_t*)&h0; o.y = *(uint32_t*)&h1;
    o.z = *(uint32_t*)&h2; o.w = *(uint32_t*)&h3;
    *(uint4*)(dst + i) = o;
}

// ---------------------------------------------------------------------------
// fp16 tensor-core GEMM + bias + activations.
//   y[m,n] = sum_k A[m,k] W[n,k] + b[n];  gate 0 -> tanh -> g_z,
//   gate 1 -> sigmoid -> g_f, gate 2 -> sigmoid -> out (scan scales later).
// 128x128x32 tiles, 3-stage cp.async, ldmatrix feeds, m16n8k16 HMMA.
// ---------------------------------------------------------------------------
__global__ __launch_bounds__(256) void qrnn_gemm_h(
    const float* __restrict__ bias, float* __restrict__ out)
{
    extern __shared__ char smem[];
    const int tid  = threadIdx.x;
    const int lane = tid & 31;
    const int wid  = tid >> 5;
    const int wm   = wid >> 2;        // 0..1 : 64 rows
    const int wn   = wid & 3;         // 0..3 : 32 cols
    const int m0 = blockIdx.y * BM;
    const int n0 = blockIdx.x * BN;
    const uint32_t sbase = smem_u32(smem);

    float acc[4][4][4];
    #pragma unroll
    for (int mi = 0; mi < 4; mi++)
        #pragma unroll
        for (int ni = 0; ni < 4; ni++)
            #pragma unroll
            for (int r = 0; r < 4; r++) acc[mi][ni][r] = 0.0f;

    // stage loader: A rows (m0..+127) and W rows (n0..+127), 32 halves each
    auto load_stage = [&](int kt, int buf) {
        const int k0 = kt * BK;
        const uint32_t st = sbase + buf * STAGE_BYTES;
        #pragma unroll
        for (int i = 0; i < 4; i++) {
            int id = tid + i * 256;          // 0..1023
            int isB = id >> 9;               // 0: A, 1: B
            int r   = (id >> 2) & 127;
            int ch  = id & 3;                // 16B chunk (8 halves)
            uint32_t dstofs = (uint32_t)(isB * STAGE_HALVES + r * RS + ch * 8) * 2;
            const __half* gp = isB
                ? (g_Wh + (size_t)(n0 + r) * K + k0 + ch * 8)
                : (g_Ah + (size_t)(m0 + r) * K + k0 + ch * 8);
            cp_async16(st + dstofs, gp);
        }
        asm volatile("cp.async.commit_group;\n" ::: "memory");
    };

    load_stage(0, 0);
    load_stage(1, 1);

    for (int kt = 0; kt < NK; kt++) {
        if (kt + STAGES - 1 < NK) load_stage(kt + STAGES - 1, (kt + STAGES - 1) % STAGES);
        if (kt < NK - 1) asm volatile("cp.async.wait_group 1;\n" ::: "memory");
        else             asm volatile("cp.async.wait_group 0;\n" ::: "memory");
        __syncthreads();

        const uint32_t aB = sbase + (kt % STAGES) * STAGE_BYTES;
        const uint32_t bB = aB + STAGE_HALVES * 2;

        #pragma unroll
        for (int ks = 0; ks < 2; ks++) {
            uint32_t afr[4][4], bfr[4][2];
            // A frags: 4 x ldmatrix.x4
            #pragma unroll
            for (int mi = 0; mi < 4; mi++) {
                int m   = wm * 64 + mi * 16;
                int row = m + (lane & 7) + 8 * ((lane >> 3) & 1);
                int kof = ks * 16 + 8 * (lane >> 4);
                ldmatrix_x4(afr[mi], aB + (uint32_t)(row * RS + kof) * 2);
            }
            // B frags: 2 x ldmatrix.x4 cover 4 n-frags
            #pragma unroll
            for (int nb = 0; nb < 2; nb++) {
                int n   = wn * 32 + nb * 16;
                int row = n + (lane & 7) + 8 * (lane >> 4);
                int kof = ks * 16 + 8 * ((lane >> 3) & 1);
                uint32_t t[4];
                ldmatrix_x4(t, bB + (uint32_t)(row * RS + kof) * 2);
                bfr[nb * 2][0] = t[0]; bfr[nb * 2][1] = t[1];
                bfr[nb * 2 + 1][0] = t[2]; bfr[nb * 2 + 1][1] = t[3];
            }
            #pragma unroll
            for (int mi = 0; mi < 4; mi++)
                #pragma unroll
                for (int ni = 0; ni < 4; ni++)
                    mma16816(acc[mi][ni], afr[mi], bfr[ni]);
        }
        __syncthreads();
    }

    // ---- epilogue: bias + activation, direct float2 stores
    const int gate  = n0 >> 10;
    const int hbase = n0 & (H_ - 1);
    float* dst = (gate == 0) ? g_z : ((gate == 1) ? g_f : out);

    #pragma unroll
    for (int mi = 0; mi < 4; mi++) {
        int r0 = m0 + wm * 64 + mi * 16 + (lane >> 2);
        #pragma unroll
        for (int ni = 0; ni < 4; ni++) {
            int c  = wn * 32 + ni * 8 + (lane & 3) * 2;
            float bx = __ldg(&bias[n0 + c]);
            float by = __ldg(&bias[n0 + c + 1]);
            float v0 = acc[mi][ni][0] + bx, v1 = acc[mi][ni][1] + by;
            float v2 = acc[mi][ni][2] + bx, v3 = acc[mi][ni][3] + by;
            if (gate == 0) { v0 = ftanh(v0); v1 = ftanh(v1); v2 = ftanh(v2); v3 = ftanh(v3); }
            else           { v0 = fsig(v0);  v1 = fsig(v1);  v2 = fsig(v2);  v3 = fsig(v3); }
            float2 lo = make_float2(v0, v1), hi = make_float2(v2, v3);
            *(float2*)&dst[(size_t)r0 * H_ + hbase + c]       = lo;
            *(float2*)&dst[(size_t)(r0 + 8) * H_ + hbase + c] = hi;
        }
    }
}

// ---------------------------------------------------------------------------
// Sequential recurrence: one thread per (b, h) chain, coalesced over h.
// ---------------------------------------------------------------------------
__global__ __launch_bounds__(256) void qrnn_scan(float* __restrict__ out, int write_clast)
{
    const int idx = blockIdx.x * blockDim.x + threadIdx.x;   // 0 .. B*H-1
    const int b = idx >> 10;
    const int h = idx & (H_ - 1);
    const size_t base = (size_t)b * S_ * H_ + h;

    constexpr int U = 16;
    float z[U], f[U], o[U];
    #pragma unroll
    for (int j = 0; j < U; j++) {
        size_t p = base + (size_t)j * H_;
        z[j] = g_z[p]; f[j] = g_f[p]; o[j] = out[p];
    }

    float hh = 0.0f;
    for (int t = 0; t < S_; t += U) {
        float zn[U], fn[U], on[U];
        if (t + U < S_) {
            #pragma unroll
            for (int j = 0; j < U; j++) {
                size_t p = base + (size_t)(t + U + j) * H_;
                zn[j] = g_z[p]; fn[j] = g_f[p]; on[j] = out[p];
            }
        }
        #pragma unroll
        for (int j = 0; j < U; j++) {
            hh = fmaf(f[j], z[j] - hh, hh);
            out[base + (size_t)(t + j) * H_] = o[j] * hh;
        }
        #pragma unroll
        for (int j = 0; j < U; j++) { z[j] = zn[j]; f[j] = fn[j]; o[j] = on[j]; }
    }

    if (write_clast) out[(size_t)B_ * S_ * H_ + idx] = hh;
}

// ---------------------------------------------------------------------------
extern "C" void kernel_launch(void* const* d_in, const int* in_sizes, int n_in,
                              void* d_out, int out_size)
{
    const float* inp  = (const float*)d_in[0];   // [B, S, D] f32
    const float* Wt   = (const float*)d_in[1];   // [3H, D]   f32
    const float* bias = (const float*)d_in[2];   // [3H]      f32
    float* out = (float*)d_out;

    // fp32 -> fp16 staging
    {
        int nA = M * K;
        int nW = N3 * K;
        __half* dA; __half* dW;
        cudaGetSymbolAddress((void**)&dA, g_Ah);
        cudaGetSymbolAddress((void**)&dW, g_Wh);
        cvt_f2h<<<(nA / 8 + 255) / 256, 256>>>(inp, dA, nA);
        cvt_f2h<<<(nW / 8 + 255) / 256, 256>>>(Wt, dW, nW);
    }

    cudaFuncSetAttribute(qrnn_gemm_h, cudaFuncAttributeMaxDynamicSharedMemorySize, SMEM_TOTAL);
    dim3 grid(N3 / BN, M / BM);   // x fastest -> 24 n-tiles reuse each A panel via L2
    qrnn_gemm_h<<<grid, 256, SMEM_TOTAL>>>(bias, out);

    const long long need = (long long)M * H_ + (long long)B_ * H_;
    int write_clast = ((long long)out_size >= need) ? 1 : 0;
    qrnn_scan<<<(B_ * H_) / 256, 256>>>(out, write_clast);
}